// round 14
// baseline (speedup 1.0000x reference)
#include <cuda_runtime.h>
#include <cuda_bf16.h>
#include <cstdint>
#include <math.h>

#define H_ 256
#define W_ 256
#define B_ 8
#define HW (H_ * W_)
#define KF 11
#define THRESH 0.2f

// ---------------------------------------------------------------------------
// Device scratch (no allocation allowed)
// ---------------------------------------------------------------------------
__device__ __nv_bfloat16 g_bufA[(size_t)B_ * 128 * HW];   // NHWC activations ping
__device__ __nv_bfloat16 g_bufB[(size_t)B_ * 128 * HW];   // NHWC pong / fp32 scratch
// Fragment-packed weights: [ky][s][n8][lane] -> uint2 (b0,b1 regs of m16n8k16)
__device__ uint2 g_wt2[3 * 12 * 8 * 32];     // CIN=64,  NP=64
__device__ uint2 g_wt3[3 * 12 * 16 * 32];    // CIN=64,  NP=128
__device__ uint2 g_wt4[3 * 24 * 16 * 32];    // CIN=128, NP=128
__device__ uint2 g_wt5[3 * 24 * 8 * 32];     // CIN=128, NP=64
__device__ uint2 g_wtp[3 * 12 * 4 * 32];     // CIN=64,  NP=32

__device__ __forceinline__ uint32_t smem_u32(const void* p) {
    uint32_t a;
    asm("{ .reg .u64 t; cvta.to.shared.u64 t, %1; cvt.u32.u64 %0, t; }" : "=r"(a) : "l"(p));
    return a;
}

__device__ __forceinline__ void ldmatrix_x4(uint32_t* a, uint32_t addr) {
    asm volatile("ldmatrix.sync.aligned.m8n8.x4.shared.b16 {%0,%1,%2,%3}, [%4];"
                 : "=r"(a[0]), "=r"(a[1]), "=r"(a[2]), "=r"(a[3]) : "r"(addr));
}

__device__ __forceinline__ void mma_bf16(float* d, const uint32_t* a, const uint32_t* b) {
    asm volatile(
        "mma.sync.aligned.m16n8k16.row.col.f32.bf16.bf16.f32 "
        "{%0,%1,%2,%3}, {%4,%5,%6,%7}, {%8,%9}, {%0,%1,%2,%3};"
        : "+f"(d[0]), "+f"(d[1]), "+f"(d[2]), "+f"(d[3])
        : "r"(a[0]), "r"(a[1]), "r"(a[2]), "r"(a[3]), "r"(b[0]), "r"(b[1]));
}

__device__ __forceinline__ void cp16(uint32_t dst, const void* src, bool pred) {
    asm volatile("cp.async.cg.shared.global [%0], [%1], 16, %2;"
                 :: "r"(dst), "l"(src), "r"(pred ? 16 : 0));
}
#define CP_COMMIT() asm volatile("cp.async.commit_group;" ::: "memory")
#define CP_WAIT0()  asm volatile("cp.async.wait_group 0;" ::: "memory")

// ---------------------------------------------------------------------------
// Fragment-order weight packing.
// For step s, n-group n8, lane: b0 = pair(k0, k0+1), b1 = pair(k0+8, k0+9)
// with k0 = s*16 + (lane&3)*2, n = n8*8 + (lane>>2); k -> kx=k/CIN, ci=k%CIN.
// ---------------------------------------------------------------------------
template <int CIN, int COUT, int NP>
__device__ __forceinline__ void packfrag(const float* __restrict__ w, uint2* __restrict__ wt, int i) {
    constexpr int NSTEP = 3 * CIN / 16;
    constexpr int NPG = NP / 8;
    int lane = i & 31;
    int n8 = (i >> 5) % NPG;
    int s = (i >> 5) / NPG % NSTEP;
    int ky = i / (32 * NPG * NSTEP);
    int n = n8 * 8 + (lane >> 2);
    int k0 = s * 16 + (lane & 3) * 2;
    float v[4];
#pragma unroll
    for (int j = 0; j < 4; j++) {
        int k = k0 + (j >> 1) * 8 + (j & 1);
        int kx = k / CIN, ci = k % CIN;
        v[j] = (n < COUT) ? w[((size_t)n * CIN + ci) * 9 + ky * 3 + kx] : 0.f;
    }
    __nv_bfloat162 lo = __floats2bfloat162_rn(v[0], v[1]);
    __nv_bfloat162 hi = __floats2bfloat162_rn(v[2], v[3]);
    uint2 r;
    r.x = *(uint32_t*)&lo;
    r.y = *(uint32_t*)&hi;
    wt[i] = r;
}

__global__ void packall_kernel(const float* __restrict__ w2, const float* __restrict__ w3,
                               const float* __restrict__ w4, const float* __restrict__ w5,
                               const float* __restrict__ wh, const float* __restrict__ wv,
                               uint2* __restrict__ wt2, uint2* __restrict__ wt3,
                               uint2* __restrict__ wt4, uint2* __restrict__ wt5,
                               uint2* __restrict__ wtp) {
    constexpr int N2 = 3 * 12 * 8 * 32;
    constexpr int N3 = 3 * 12 * 16 * 32;
    constexpr int N4 = 3 * 24 * 16 * 32;
    constexpr int N5 = 3 * 24 * 8 * 32;
    constexpr int NPP = 3 * 12 * 4 * 32;
    int i = blockIdx.x * 256 + threadIdx.x;
    if (i < N2) { packfrag<64, 64, 64>(w2, wt2, i); return; }
    i -= N2;
    if (i < N3) { packfrag<64, 128, 128>(w3, wt3, i); return; }
    i -= N3;
    if (i < N4) { packfrag<128, 128, 128>(w4, wt4, i); return; }
    i -= N4;
    if (i < N5) { packfrag<128, 64, 64>(w5, wt5, i); return; }
    i -= N5;
    if (i < NPP) {
        // kpred: n 0..10 = wh, 11..21 = wv, rest 0 (CIN=64, NP=32)
        constexpr int NSTEP = 12, NPG = 4;
        int lane = i & 31;
        int n8 = (i >> 5) % NPG;
        int s = (i >> 5) / NPG % NSTEP;
        int ky = i / (32 * NPG * NSTEP);
        int n = n8 * 8 + (lane >> 2);
        int k0 = s * 16 + (lane & 3) * 2;
        float v[4];
#pragma unroll
        for (int j = 0; j < 4; j++) {
            int k = k0 + (j >> 1) * 8 + (j & 1);
            int kx = k / 64, ci = k % 64;
            float val = 0.f;
            if (n < KF)          val = wh[((size_t)n * 64 + ci) * 9 + ky * 3 + kx];
            else if (n < 2 * KF) val = wv[((size_t)(n - KF) * 64 + ci) * 9 + ky * 3 + kx];
            v[j] = val;
        }
        __nv_bfloat162 lo = __floats2bfloat162_rn(v[0], v[1]);
        __nv_bfloat162 hi = __floats2bfloat162_rn(v[2], v[3]);
        uint2 r;
        r.x = *(uint32_t*)&lo;
        r.y = *(uint32_t*)&hi;
        wtp[i] = r;
    }
}

// ---------------------------------------------------------------------------
// conv1: 4 -> 64, fp32 direct, NCHW fp32 in -> bf16 NHWC out
// ---------------------------------------------------------------------------
__global__ __launch_bounds__(256)
void conv1_kernel(const float* __restrict__ rgb, const float* __restrict__ depth,
                  const float* __restrict__ w1, const float* __restrict__ b1,
                  __nv_bfloat16* __restrict__ out) {
    __shared__ float sw[64 * 36];
    __shared__ float sb[64];
    int tid = threadIdx.x;
    for (int i = tid; i < 64 * 36; i += 256) sw[i] = w1[i];
    if (tid < 64) sb[tid] = b1[tid];
    __syncthreads();

    int gp = blockIdx.x * 256 + tid;
    int x = gp % W_;
    int y = (gp / W_) % H_;
    int b = gp / HW;

    float acc[64];
#pragma unroll
    for (int o = 0; o < 64; o++) acc[o] = sb[o];

    for (int ci = 0; ci < 4; ci++) {
        const float* plane = (ci < 3) ? rgb + ((size_t)b * 3 + ci) * HW
                                      : depth + (size_t)b * HW;
#pragma unroll
        for (int dy = -1; dy <= 1; dy++) {
#pragma unroll
            for (int dx = -1; dx <= 1; dx++) {
                int yy = y + dy, xx = x + dx;
                float v = (yy >= 0 && yy < H_ && xx >= 0 && xx < W_) ? plane[yy * W_ + xx] : 0.f;
                int widx = ci * 9 + (dy + 1) * 3 + (dx + 1);
#pragma unroll
                for (int o = 0; o < 64; o++) acc[o] = fmaf(sw[o * 36 + widx], v, acc[o]);
            }
        }
    }
    __nv_bfloat16* op = out + (size_t)gp * 64;
#pragma unroll
    for (int o = 0; o < 64; o += 2) {
        __nv_bfloat162 h = __floats2bfloat162_rn(fmaxf(acc[o], 0.f), fmaxf(acc[o + 1], 0.f));
        *(__nv_bfloat162*)(op + o) = h;
    }
}

// ---------------------------------------------------------------------------
// Stage one ky row's A im2col strip (PXT+2 pixels x C) via cp.async
// ---------------------------------------------------------------------------
template <int C, int PXT, int THREADS>
__device__ __forceinline__ void stage_A(const __nv_bfloat16* __restrict__ in,
                                        uint32_t sA_u, int b, int y, int ky,
                                        int x0, int tid) {
    constexpr int SA = C + 8;
    constexpr int CH8 = C / 8;
    const int yy = y + ky - 1;
    const bool rowok = ((unsigned)yy < H_);
    const __nv_bfloat16* inrow = in + (((size_t)b * H_ + (rowok ? yy : 0)) * W_) * C;
    for (int it = tid; it < (PXT + 2) * CH8; it += THREADS) {
        int p = it / CH8;
        int c8 = it - p * CH8;
        int xx = x0 + p - 1;
        bool ok = rowok && ((unsigned)xx < W_);
        cp16(sA_u + (p * SA + c8 * 8) * 2, inrow + (size_t)(ok ? xx : 0) * C + c8 * 8, ok);
    }
}

// ---------------------------------------------------------------------------
// Compute one ky row's MMA contribution: A from smem (ldmatrix), B from gmem
// fragments (__ldg uint2, L1/L2-resident). Warp tile = MB*16 px x 32 n.
// NO barriers inside — caller stages all rows up front so ptxas can pipeline
// across the whole 3-ky chain.
// ---------------------------------------------------------------------------
template <int C, int MB, int NP>
__device__ __forceinline__ void compute_ky(uint32_t sA_u, const uint2* __restrict__ wtF,
                                           int ky, int n8_0, int wm, int wn, int lane,
                                           float (*acc)[4] /* [MB*4][4] */) {
    constexpr int SA = C + 8;
    constexpr int NSTEP = 3 * C / 16;
    constexpr int KXW = C / 16;
    constexpr int NBK = 4;      // warp n-width fixed at 32
    constexpr int NPG = NP / 8;

    const int lane_row = lane & 15;
    const int colsel = (lane >> 4) * 8;
    const uint2* wbase = wtF + ((size_t)ky * NSTEP * NPG + n8_0 + wn * NBK) * 32 + lane;
    const int mrow0 = wm * (MB * 16);

#pragma unroll
    for (int s = 0; s < NSTEP; s++) {
        const int kx = s / KXW;
        const int c0 = (s - kx * KXW) * 16;
        uint32_t afr[MB][4];
#pragma unroll
        for (int mb = 0; mb < MB; mb++) {
            uint32_t addr = sA_u +
                ((mrow0 + mb * 16 + lane_row + kx) * SA + c0 + colsel) * 2;
            ldmatrix_x4(afr[mb], addr);
        }
        uint32_t bfr[NBK][2];
#pragma unroll
        for (int nb = 0; nb < NBK; nb++) {
            uint2 bv = __ldg(wbase + ((size_t)s * NPG + nb) * 32);
            bfr[nb][0] = bv.x;
            bfr[nb][1] = bv.y;
        }
#pragma unroll
        for (int mb = 0; mb < MB; mb++)
#pragma unroll
            for (int nb = 0; nb < NBK; nb++)
                mma_bf16(acc[mb * NBK + nb], afr[mb], bfr[nb]);
    }
}

// ---------------------------------------------------------------------------
// Implicit-GEMM 3x3 conv via mma.sync. All 3 ky rows staged up front (3 smem
// buffers, ONE wait + ONE barrier), then barrier-free 3-phase compute chain.
// CTA: (MW*MB*16) px x (NW*32) n. Warp = MB*16 px x 32 n.
// ---------------------------------------------------------------------------
template <int C, int MW, int NW, int MB, int NP, bool RELU, bool F32OUT>
__global__ __launch_bounds__(MW * NW * 32)
void convmma_kernel(const __nv_bfloat16* __restrict__ in,
                    const uint2* __restrict__ wtF,
                    const float* __restrict__ bias,
                    void* __restrict__ outv) {
    constexpr int THREADS = MW * NW * 32;
    constexpr int PXT = MW * MB * 16;
    constexpr int NTILE = NW * 32;
    constexpr int SA = C + 8;
    constexpr int NBK = 4;
    constexpr int ASZ = (PXT + 2) * SA * 2;

    extern __shared__ char smem_raw[];
    const uint32_t sA0_u = smem_u32(smem_raw);

    __shared__ float s_bias[NTILE];

    const int tid = threadIdx.x;
    const int wid = tid >> 5;
    const int lane = tid & 31;
    const int wm = wid % MW;
    const int wn = wid / MW;
    const int x0 = blockIdx.x * PXT;
    const int y = blockIdx.y;
    constexpr int NTILES = NP / NTILE;
    const int b = blockIdx.z / NTILES;
    const int n0 = (blockIdx.z % NTILES) * NTILE;
    const int n8_0 = n0 / 8;

    if (!F32OUT && tid < NTILE) s_bias[tid] = bias[n0 + tid];

    float acc[MB * NBK][4];
#pragma unroll
    for (int i = 0; i < MB * NBK; i++)
#pragma unroll
        for (int q = 0; q < 4; q++) acc[i][q] = 0.f;

    // Stage ALL 3 ky rows, then one wait + one barrier.
    stage_A<C, PXT, THREADS>(in, sA0_u,            b, y, 0, x0, tid);
    stage_A<C, PXT, THREADS>(in, sA0_u + ASZ,      b, y, 1, x0, tid);
    stage_A<C, PXT, THREADS>(in, sA0_u + 2 * ASZ,  b, y, 2, x0, tid);
    CP_COMMIT();
    CP_WAIT0();
    __syncthreads();

    // Barrier-free compute chain — ptxas pipelines across phases.
    compute_ky<C, MB, NP>(sA0_u,           wtF, 0, n8_0, wm, wn, lane, acc);
    compute_ky<C, MB, NP>(sA0_u + ASZ,     wtF, 1, n8_0, wm, wn, lane, acc);
    compute_ky<C, MB, NP>(sA0_u + 2 * ASZ, wtF, 2, n8_0, wm, wn, lane, acc);

    // ---- epilogue ----
    const int g = lane >> 2;
    const int cpair = (lane & 3) * 2;
#pragma unroll
    for (int mb = 0; mb < MB; mb++) {
#pragma unroll
        for (int half = 0; half < 2; half++) {
            int m = wm * (MB * 16) + mb * 16 + g + half * 8;
            size_t pix = ((size_t)b * H_ + y) * W_ + x0 + m;
#pragma unroll
            for (int nb = 0; nb < NBK; nb++) {
                int col = wn * 32 + nb * 8 + cpair;
                float f0 = acc[mb * NBK + nb][half * 2 + 0];
                float f1 = acc[mb * NBK + nb][half * 2 + 1];
                if (F32OUT) {
                    float* op = (float*)outv + pix * NP + n0 + col;
                    *(float2*)op = make_float2(f0, f1);
                } else {
                    f0 += s_bias[col];
                    f1 += s_bias[col + 1];
                    if (RELU) { f0 = fmaxf(f0, 0.f); f1 = fmaxf(f1, 0.f); }
                    __nv_bfloat162 h = __floats2bfloat162_rn(f0, f1);
                    __nv_bfloat16* op = (__nv_bfloat16*)outv + pix * NP + n0 + col;
                    *(uint32_t*)op = *(uint32_t*)&h;
                }
            }
        }
    }
}

// ---------------------------------------------------------------------------
// softmax over logits [B,H,W,32] fp32 -> kh, kv NCHW fp32
// ---------------------------------------------------------------------------
__global__ __launch_bounds__(256)
void softmax_kernel(const float* __restrict__ logits,
                    const float* __restrict__ bh, const float* __restrict__ bv,
                    float* __restrict__ kh_out, float* __restrict__ kv_out) {
    __shared__ float sbh[KF], sbv[KF];
    int tid = threadIdx.x;
    if (tid < KF) { sbh[tid] = bh[tid]; sbv[tid] = bv[tid]; }
    __syncthreads();

    int gp = blockIdx.x * 256 + tid;
    int px = gp % HW;
    int b = gp / HW;
    int y = px / W_, x = px % W_;
    const float* lp = logits + (size_t)gp * 32;

    float l[KF];
#pragma unroll
    for (int i = 0; i < KF; i++) l[i] = lp[i] + sbh[i];
    float mx = l[0];
#pragma unroll
    for (int i = 1; i < KF; i++) mx = fmaxf(mx, l[i]);
    float e[KF], s = 0.f;
#pragma unroll
    for (int i = 0; i < KF; i++) { e[i] = expf(l[i] - mx); s += e[i]; }
    float inv = 1.f / s;
#pragma unroll
    for (int i = 0; i < KF; i++)
        kh_out[(((size_t)b * KF + i) * H_ + y) * W_ + x] = e[i] * inv;

#pragma unroll
    for (int i = 0; i < KF; i++) l[i] = lp[KF + i] + sbv[i];
    mx = l[0];
#pragma unroll
    for (int i = 1; i < KF; i++) mx = fmaxf(mx, l[i]);
    s = 0.f;
#pragma unroll
    for (int i = 0; i < KF; i++) { e[i] = expf(l[i] - mx); s += e[i]; }
    inv = 1.f / s;
#pragma unroll
    for (int i = 0; i < KF; i++)
        kv_out[(((size_t)b * KF + i) * H_ + y) * W_ + x] = e[i] * inv;
}

// ---------------------------------------------------------------------------
// Separable blur + composite (fp32)
// ---------------------------------------------------------------------------
__global__ __launch_bounds__(256)
void hblur_kernel(const float* __restrict__ rgb, const float* __restrict__ kh,
                  float* __restrict__ hout) {
    __shared__ float srow[3][W_ + 10];
    const int x = threadIdx.x;
    const int y = blockIdx.x;
    const int b = blockIdx.y;

#pragma unroll
    for (int c = 0; c < 3; c++)
        srow[c][x + 5] = rgb[(((size_t)b * 3 + c) * H_ + y) * W_ + x];
    if (x < 5) {
#pragma unroll
        for (int c = 0; c < 3; c++) { srow[c][x] = 0.f; srow[c][W_ + 5 + x] = 0.f; }
    }
    __syncthreads();

    float k[KF];
#pragma unroll
    for (int i = 0; i < KF; i++)
        k[i] = kh[(((size_t)b * KF + i) * H_ + y) * W_ + x];

#pragma unroll
    for (int c = 0; c < 3; c++) {
        float s = 0.f;
#pragma unroll
        for (int i = 0; i < KF; i++) s = fmaf(k[i], srow[c][x + i], s);
        hout[(((size_t)b * 3 + c) * H_ + y) * W_ + x] = s;
    }
}

__global__ __launch_bounds__(256)
void vblur_kernel(const float* __restrict__ hbuf, const float* __restrict__ kv,
                  const float* __restrict__ rgb, const float* __restrict__ depth,
                  float* __restrict__ fin, float* __restrict__ blur,
                  float* __restrict__ mask) {
    const int x = threadIdx.x;
    const int y = blockIdx.x;
    const int b = blockIdx.y;

    float k[KF];
#pragma unroll
    for (int i = 0; i < KF; i++)
        k[i] = kv[(((size_t)b * KF + i) * H_ + y) * W_ + x];

    float d = depth[((size_t)b * H_ + y) * W_ + x];
    float m = (d > THRESH) ? 1.f : 0.f;

#pragma unroll
    for (int c = 0; c < 3; c++) {
        float s = 0.f;
#pragma unroll
        for (int i = 0; i < KF; i++) {
            int yy = y - 5 + i;
            if (yy >= 0 && yy < H_)
                s = fmaf(k[i], hbuf[(((size_t)b * 3 + c) * H_ + yy) * W_ + x], s);
        }
        size_t oidx = (((size_t)b * 3 + c) * H_ + y) * W_ + x;
        float r = rgb[oidx];
        blur[oidx] = s;
        fin[oidx] = m * r + (1.f - m) * s;
    }
    mask[((size_t)b * H_ + y) * W_ + x] = m;
}

// ---------------------------------------------------------------------------
extern "C" void kernel_launch(void* const* d_in, const int* in_sizes, int n_in,
                              void* d_out, int out_size) {
    const float* rgb   = (const float*)d_in[0];
    const float* depth = (const float*)d_in[1];
    const float* w1 = (const float*)d_in[2];
    const float* b1 = (const float*)d_in[3];
    const float* w2 = (const float*)d_in[4];
    const float* b2 = (const float*)d_in[5];
    const float* w3 = (const float*)d_in[6];
    const float* b3 = (const float*)d_in[7];
    const float* w4 = (const float*)d_in[8];
    const float* b4 = (const float*)d_in[9];
    const float* w5 = (const float*)d_in[10];
    const float* b5 = (const float*)d_in[11];
    const float* wh = (const float*)d_in[12];
    const float* bh = (const float*)d_in[13];
    const float* wv = (const float*)d_in[14];
    const float* bv = (const float*)d_in[15];

    float* out = (float*)d_out;
    float* fin_o  = out;
    float* blur_o = out + (size_t)B_ * 3 * HW;
    float* kh_o   = out + (size_t)2 * B_ * 3 * HW;
    float* kv_o   = kh_o + (size_t)B_ * KF * HW;
    float* mask_o = kv_o + (size_t)B_ * KF * HW;

    __nv_bfloat16 *bufA, *bufB;
    uint2 *wt2, *wt3, *wt4, *wt5, *wtp;
    cudaGetSymbolAddress((void**)&bufA, g_bufA);
    cudaGetSymbolAddress((void**)&bufB, g_bufB);
    cudaGetSymbolAddress((void**)&wt2, g_wt2);
    cudaGetSymbolAddress((void**)&wt3, g_wt3);
    cudaGetSymbolAddress((void**)&wt4, g_wt4);
    cudaGetSymbolAddress((void**)&wt5, g_wt5);
    cudaGetSymbolAddress((void**)&wtp, g_wtp);

    // smem: 3 stages of (PXT+2)x(C+8) bf16
    const int S_c2 = 3 * 258 * 72 * 2;    // conv2: PXT=256, C=64  (111456 B)
    const int S_c3 = 3 * 130 * 72 * 2;    // conv3: PXT=128, C=64  (56160 B)
    const int S_c4 = 3 * 130 * 136 * 2;   // conv4: PXT=128, C=128 (106080 B)
    const int S_c5 = 3 * 130 * 136 * 2;   // conv5: PXT=128, C=128
    const int S_kp = 3 * 258 * 72 * 2;    // kpred: PXT=256, C=64

    cudaFuncSetAttribute((const void*)convmma_kernel<64, 4, 2, 4, 64, true, false>,
                         cudaFuncAttributeMaxDynamicSharedMemorySize, S_c2);
    cudaFuncSetAttribute((const void*)convmma_kernel<64, 2, 4, 4, 128, true, false>,
                         cudaFuncAttributeMaxDynamicSharedMemorySize, S_c3);
    cudaFuncSetAttribute((const void*)convmma_kernel<128, 2, 4, 4, 128, true, false>,
                         cudaFuncAttributeMaxDynamicSharedMemorySize, S_c4);
    cudaFuncSetAttribute((const void*)convmma_kernel<128, 2, 2, 4, 64, true, false>,
                         cudaFuncAttributeMaxDynamicSharedMemorySize, S_c5);
    cudaFuncSetAttribute((const void*)convmma_kernel<64, 8, 1, 2, 32, false, true>,
                         cudaFuncAttributeMaxDynamicSharedMemorySize, S_kp);

    // launch 0: fused fragment-order weight packing
    {
        int total = (3 * 12 * 8 + 3 * 12 * 16 + 3 * 24 * 16 + 3 * 24 * 8 + 3 * 12 * 4) * 32;
        packall_kernel<<<(total + 255) / 256, 256>>>(w2, w3, w4, w5, wh, wv,
                                                     wt2, wt3, wt4, wt5, wtp);
    }
    // launch 1: conv1 fp32 direct -> bf16 NHWC (bufA, 64ch)
    conv1_kernel<<<B_ * HW / 256, 256>>>(rgb, depth, w1, b1, bufA);

    // launch 2: conv2 64->64 (256px x 64n per CTA)
    convmma_kernel<64, 4, 2, 4, 64, true, false>
        <<<dim3(1, H_, B_), 256, S_c2>>>(bufA, wt2, b2, bufB);
    // launch 3: conv3 64->128 (128px x 128n per CTA)
    convmma_kernel<64, 2, 4, 4, 128, true, false>
        <<<dim3(2, H_, B_), 256, S_c3>>>(bufB, wt3, b3, bufA);
    // launch 4: conv4 128->128 (128px x 128n per CTA)
    convmma_kernel<128, 2, 4, 4, 128, true, false>
        <<<dim3(2, H_, B_), 256, S_c4>>>(bufA, wt4, b4, bufB);
    // launch 5: conv5 128->64 (128px x 64n per CTA, 128 threads)
    convmma_kernel<128, 2, 2, 4, 64, true, false>
        <<<dim3(2, H_, B_), 128, S_c5>>>(bufB, wt5, b5, bufA);
    // launch 6: kpred 64->32 logits (256px x 32n per CTA, fp32 out)
    convmma_kernel<64, 8, 1, 2, 32, false, true>
        <<<dim3(1, H_, B_), 256, S_kp>>>(bufA, wtp, nullptr, (float*)bufB);
    // launch 7: softmax
    softmax_kernel<<<B_ * HW / 256, 256>>>((const float*)bufB, bh, bv, kh_o, kv_o);
    // launch 8/9: blur + composite
    hblur_kernel<<<dim3(H_, B_), 256>>>(rgb, kh_o, (float*)bufA);
    vblur_kernel<<<dim3(H_, B_), 256>>>((float*)bufA, kv_o, rgb, depth, fin_o, blur_o, mask_o);
}

// round 15
// speedup vs baseline: 1.2053x; 1.2053x over previous
#include <cuda_runtime.h>
#include <cuda_bf16.h>
#include <cstdint>
#include <math.h>

#define H_ 256
#define W_ 256
#define B_ 8
#define HW (H_ * W_)
#define KF 11
#define THRESH 0.2f

// ---------------------------------------------------------------------------
// Device scratch (no allocation allowed)
// ---------------------------------------------------------------------------
__device__ __nv_bfloat16 g_bufA[(size_t)B_ * 128 * HW];   // NHWC activations ping
__device__ __nv_bfloat16 g_bufB[(size_t)B_ * 128 * HW];   // NHWC pong / x16 input / fp32 scratch
// Fragment-packed weights: [ky][s][n8][lane] -> uint2 (b0,b1 regs of m16n8k16)
__device__ uint2 g_wt1[3 * 3 * 8 * 32];      // CIN=16(pad4), NP=64
__device__ uint2 g_wt2[3 * 12 * 8 * 32];     // CIN=64,  NP=64
__device__ uint2 g_wt3[3 * 12 * 16 * 32];    // CIN=64,  NP=128
__device__ uint2 g_wt4[3 * 24 * 16 * 32];    // CIN=128, NP=128
__device__ uint2 g_wt5[3 * 24 * 8 * 32];     // CIN=128, NP=64
__device__ uint2 g_wtp[3 * 12 * 4 * 32];     // CIN=64,  NP=32

__device__ __forceinline__ uint32_t smem_u32(const void* p) {
    uint32_t a;
    asm("{ .reg .u64 t; cvta.to.shared.u64 t, %1; cvt.u32.u64 %0, t; }" : "=r"(a) : "l"(p));
    return a;
}

__device__ __forceinline__ void ldmatrix_x4(uint32_t* a, uint32_t addr) {
    asm volatile("ldmatrix.sync.aligned.m8n8.x4.shared.b16 {%0,%1,%2,%3}, [%4];"
                 : "=r"(a[0]), "=r"(a[1]), "=r"(a[2]), "=r"(a[3]) : "r"(addr));
}

__device__ __forceinline__ void mma_bf16(float* d, const uint32_t* a, const uint32_t* b) {
    asm volatile(
        "mma.sync.aligned.m16n8k16.row.col.f32.bf16.bf16.f32 "
        "{%0,%1,%2,%3}, {%4,%5,%6,%7}, {%8,%9}, {%0,%1,%2,%3};"
        : "+f"(d[0]), "+f"(d[1]), "+f"(d[2]), "+f"(d[3])
        : "r"(a[0]), "r"(a[1]), "r"(a[2]), "r"(a[3]), "r"(b[0]), "r"(b[1]));
}

__device__ __forceinline__ void cp16(uint32_t dst, const void* src, bool pred) {
    asm volatile("cp.async.cg.shared.global [%0], [%1], 16, %2;"
                 :: "r"(dst), "l"(src), "r"(pred ? 16 : 0));
}
#define CP_COMMIT() asm volatile("cp.async.commit_group;" ::: "memory")
#define CP_WAIT0()  asm volatile("cp.async.wait_group 0;" ::: "memory")

// ---------------------------------------------------------------------------
// Fragment-order weight packing: [ky][s][n8][lane] uint2.
// b0 = pair(k0,k0+1), b1 = pair(k0+8,k0+9); k0 = s*16+(lane&3)*2; n = n8*8+(lane>>2)
// ---------------------------------------------------------------------------
template <int CIN, int COUT, int NP>
__device__ __forceinline__ void packfrag(const float* __restrict__ w, uint2* __restrict__ wt, int i) {
    constexpr int NSTEP = 3 * CIN / 16;
    constexpr int NPG = NP / 8;
    int lane = i & 31;
    int n8 = (i >> 5) % NPG;
    int s = (i >> 5) / NPG % NSTEP;
    int ky = i / (32 * NPG * NSTEP);
    int n = n8 * 8 + (lane >> 2);
    int k0 = s * 16 + (lane & 3) * 2;
    float v[4];
#pragma unroll
    for (int j = 0; j < 4; j++) {
        int k = k0 + (j >> 1) * 8 + (j & 1);
        int kx = k / CIN, ci = k % CIN;
        v[j] = (n < COUT) ? w[((size_t)n * CIN + ci) * 9 + ky * 3 + kx] : 0.f;
    }
    __nv_bfloat162 lo = __floats2bfloat162_rn(v[0], v[1]);
    __nv_bfloat162 hi = __floats2bfloat162_rn(v[2], v[3]);
    uint2 r; r.x = *(uint32_t*)&lo; r.y = *(uint32_t*)&hi;
    wt[i] = r;
}

__global__ void packall_kernel(const float* __restrict__ w1,
                               const float* __restrict__ w2, const float* __restrict__ w3,
                               const float* __restrict__ w4, const float* __restrict__ w5,
                               const float* __restrict__ wh, const float* __restrict__ wv,
                               uint2* __restrict__ wt1,
                               uint2* __restrict__ wt2, uint2* __restrict__ wt3,
                               uint2* __restrict__ wt4, uint2* __restrict__ wt5,
                               uint2* __restrict__ wtp) {
    constexpr int N1 = 3 * 3 * 8 * 32;
    constexpr int N2 = 3 * 12 * 8 * 32;
    constexpr int N3 = 3 * 12 * 16 * 32;
    constexpr int N4 = 3 * 24 * 16 * 32;
    constexpr int N5 = 3 * 24 * 8 * 32;
    constexpr int NPP = 3 * 12 * 4 * 32;
    int i = blockIdx.x * 256 + threadIdx.x;
    if (i < N1) {
        // conv1: logical CIN=16, physical CIN=4 (channels 4..15 are zero-pad)
        constexpr int NSTEP = 3, NPG = 8;
        int lane = i & 31;
        int n8 = (i >> 5) % NPG;
        int s = (i >> 5) / NPG % NSTEP;
        int ky = i / (32 * NPG * NSTEP);
        int n = n8 * 8 + (lane >> 2);
        int k0 = s * 16 + (lane & 3) * 2;
        float v[4];
#pragma unroll
        for (int j = 0; j < 4; j++) {
            int k = k0 + (j >> 1) * 8 + (j & 1);
            int kx = k / 16, ci = k % 16;
            v[j] = (ci < 4) ? w1[((size_t)n * 4 + ci) * 9 + ky * 3 + kx] : 0.f;
        }
        __nv_bfloat162 lo = __floats2bfloat162_rn(v[0], v[1]);
        __nv_bfloat162 hi = __floats2bfloat162_rn(v[2], v[3]);
        uint2 r; r.x = *(uint32_t*)&lo; r.y = *(uint32_t*)&hi;
        wt1[i] = r;
        return;
    }
    i -= N1;
    if (i < N2) { packfrag<64, 64, 64>(w2, wt2, i); return; }
    i -= N2;
    if (i < N3) { packfrag<64, 128, 128>(w3, wt3, i); return; }
    i -= N3;
    if (i < N4) { packfrag<128, 128, 128>(w4, wt4, i); return; }
    i -= N4;
    if (i < N5) { packfrag<128, 64, 64>(w5, wt5, i); return; }
    i -= N5;
    if (i < NPP) {
        // kpred: n 0..10 = wh, 11..21 = wv, rest 0 (CIN=64, NP=32)
        constexpr int NSTEP = 12, NPG = 4;
        int lane = i & 31;
        int n8 = (i >> 5) % NPG;
        int s = (i >> 5) / NPG % NSTEP;
        int ky = i / (32 * NPG * NSTEP);
        int n = n8 * 8 + (lane >> 2);
        int k0 = s * 16 + (lane & 3) * 2;
        float v[4];
#pragma unroll
        for (int j = 0; j < 4; j++) {
            int k = k0 + (j >> 1) * 8 + (j & 1);
            int kx = k / 64, ci = k % 64;
            float val = 0.f;
            if (n < KF)          val = wh[((size_t)n * 64 + ci) * 9 + ky * 3 + kx];
            else if (n < 2 * KF) val = wv[((size_t)(n - KF) * 64 + ci) * 9 + ky * 3 + kx];
            v[j] = val;
        }
        __nv_bfloat162 lo = __floats2bfloat162_rn(v[0], v[1]);
        __nv_bfloat162 hi = __floats2bfloat162_rn(v[2], v[3]);
        uint2 r; r.x = *(uint32_t*)&lo; r.y = *(uint32_t*)&hi;
        wtp[i] = r;
    }
}

// ---------------------------------------------------------------------------
// Pack rgb+depth NCHW fp32 -> NHWC-16 bf16 (c0..2 rgb, c3 depth, c4..15 zero)
// ---------------------------------------------------------------------------
__global__ __launch_bounds__(256)
void pack_input16_kernel(const float* __restrict__ rgb, const float* __restrict__ depth,
                         __nv_bfloat16* __restrict__ out) {
    int gp = blockIdx.x * 256 + threadIdx.x;
    int px = gp % HW;
    int b = gp / HW;
    float r = rgb[((size_t)b * 3 + 0) * HW + px];
    float g = rgb[((size_t)b * 3 + 1) * HW + px];
    float bl = rgb[((size_t)b * 3 + 2) * HW + px];
    float d = depth[(size_t)b * HW + px];
    __nv_bfloat16* op = out + (size_t)gp * 16;
    __nv_bfloat162 p0 = __floats2bfloat162_rn(r, g);
    __nv_bfloat162 p1 = __floats2bfloat162_rn(bl, d);
    uint4 v0;
    v0.x = *(uint32_t*)&p0;
    v0.y = *(uint32_t*)&p1;
    v0.z = 0u; v0.w = 0u;
    *(uint4*)op = v0;
    *(uint4*)(op + 8) = make_uint4(0u, 0u, 0u, 0u);
}

// ---------------------------------------------------------------------------
// Stage one ky row's A im2col strip (PXT+2 pixels x C) via cp.async
// ---------------------------------------------------------------------------
template <int C, int PXT, int THREADS>
__device__ __forceinline__ void stage_A(const __nv_bfloat16* __restrict__ in,
                                        uint32_t sA_u, int b, int y, int ky,
                                        int x0, int tid) {
    constexpr int SA = C + 8;
    constexpr int CH8 = C / 8;
    const int yy = y + ky - 1;
    const bool rowok = ((unsigned)yy < H_);
    const __nv_bfloat16* inrow = in + (((size_t)b * H_ + (rowok ? yy : 0)) * W_) * C;
    for (int it = tid; it < (PXT + 2) * CH8; it += THREADS) {
        int p = it / CH8;
        int c8 = it - p * CH8;
        int xx = x0 + p - 1;
        bool ok = rowok && ((unsigned)xx < W_);
        cp16(sA_u + (p * SA + c8 * 8) * 2, inrow + (size_t)(ok ? xx : 0) * C + c8 * 8, ok);
    }
}

// ---------------------------------------------------------------------------
// Compute one ky row's MMA contribution (barrier-free; caller staged all rows)
// ---------------------------------------------------------------------------
template <int C, int MB, int NP>
__device__ __forceinline__ void compute_ky(uint32_t sA_u, const uint2* __restrict__ wtF,
                                           int ky, int n8_0, int wm, int wn, int lane,
                                           float (*acc)[4] /* [MB*4][4] */) {
    constexpr int SA = C + 8;
    constexpr int NSTEP = 3 * C / 16;
    constexpr int KXW = C / 16;
    constexpr int NBK = 4;
    constexpr int NPG = NP / 8;

    const int lane_row = lane & 15;
    const int colsel = (lane >> 4) * 8;
    const uint2* wbase = wtF + ((size_t)ky * NSTEP * NPG + n8_0 + wn * NBK) * 32 + lane;
    const int mrow0 = wm * (MB * 16);

#pragma unroll
    for (int s = 0; s < NSTEP; s++) {
        const int kx = s / KXW;
        const int c0 = (s - kx * KXW) * 16;
        uint32_t afr[MB][4];
#pragma unroll
        for (int mb = 0; mb < MB; mb++) {
            uint32_t addr = sA_u +
                ((mrow0 + mb * 16 + lane_row + kx) * SA + c0 + colsel) * 2;
            ldmatrix_x4(afr[mb], addr);
        }
        uint32_t bfr[NBK][2];
#pragma unroll
        for (int nb = 0; nb < NBK; nb++) {
            uint2 bv = __ldg(wbase + ((size_t)s * NPG + nb) * 32);
            bfr[nb][0] = bv.x;
            bfr[nb][1] = bv.y;
        }
#pragma unroll
        for (int mb = 0; mb < MB; mb++)
#pragma unroll
            for (int nb = 0; nb < NBK; nb++)
                mma_bf16(acc[mb * NBK + nb], afr[mb], bfr[nb]);
    }
}

// ---------------------------------------------------------------------------
// Implicit-GEMM 3x3 conv: 3 rows staged up front, barrier-free compute chain.
// CTA: (MW*MB*16) px x (NW*32) n. Warp = MB*16 px x 32 n.
// ---------------------------------------------------------------------------
template <int C, int MW, int NW, int MB, int NP, bool RELU>
__global__ __launch_bounds__(MW * NW * 32)
void convmma_kernel(const __nv_bfloat16* __restrict__ in,
                    const uint2* __restrict__ wtF,
                    const float* __restrict__ bias,
                    __nv_bfloat16* __restrict__ outp) {
    constexpr int THREADS = MW * NW * 32;
    constexpr int PXT = MW * MB * 16;
    constexpr int NTILE = NW * 32;
    constexpr int SA = C + 8;
    constexpr int NBK = 4;
    constexpr int ASZ = (PXT + 2) * SA * 2;

    extern __shared__ char smem_raw[];
    const uint32_t sA0_u = smem_u32(smem_raw);

    __shared__ float s_bias[NTILE];

    const int tid = threadIdx.x;
    const int wid = tid >> 5;
    const int lane = tid & 31;
    const int wm = wid % MW;
    const int wn = wid / MW;
    const int x0 = blockIdx.x * PXT;
    const int y = blockIdx.y;
    constexpr int NTILES = NP / NTILE;
    const int b = blockIdx.z / NTILES;
    const int n0 = (blockIdx.z % NTILES) * NTILE;
    const int n8_0 = n0 / 8;

    if (tid < NTILE) s_bias[tid] = bias[n0 + tid];

    float acc[MB * NBK][4];
#pragma unroll
    for (int i = 0; i < MB * NBK; i++)
#pragma unroll
        for (int q = 0; q < 4; q++) acc[i][q] = 0.f;

    stage_A<C, PXT, THREADS>(in, sA0_u,            b, y, 0, x0, tid);
    stage_A<C, PXT, THREADS>(in, sA0_u + ASZ,      b, y, 1, x0, tid);
    stage_A<C, PXT, THREADS>(in, sA0_u + 2 * ASZ,  b, y, 2, x0, tid);
    CP_COMMIT();
    CP_WAIT0();
    __syncthreads();

    compute_ky<C, MB, NP>(sA0_u,           wtF, 0, n8_0, wm, wn, lane, acc);
    compute_ky<C, MB, NP>(sA0_u + ASZ,     wtF, 1, n8_0, wm, wn, lane, acc);
    compute_ky<C, MB, NP>(sA0_u + 2 * ASZ, wtF, 2, n8_0, wm, wn, lane, acc);

    // ---- epilogue ----
    const int g = lane >> 2;
    const int cpair = (lane & 3) * 2;
#pragma unroll
    for (int mb = 0; mb < MB; mb++) {
#pragma unroll
        for (int half = 0; half < 2; half++) {
            int m = wm * (MB * 16) + mb * 16 + g + half * 8;
            size_t pix = ((size_t)b * H_ + y) * W_ + x0 + m;
#pragma unroll
            for (int nb = 0; nb < NBK; nb++) {
                int col = wn * 32 + nb * 8 + cpair;
                float f0 = acc[mb * NBK + nb][half * 2 + 0] + s_bias[col];
                float f1 = acc[mb * NBK + nb][half * 2 + 1] + s_bias[col + 1];
                if (RELU) { f0 = fmaxf(f0, 0.f); f1 = fmaxf(f1, 0.f); }
                __nv_bfloat162 h = __floats2bfloat162_rn(f0, f1);
                __nv_bfloat16* op = outp + pix * NP + n0 + col;
                *(uint32_t*)op = *(uint32_t*)&h;
            }
        }
    }
}

// ---------------------------------------------------------------------------
// kpred: 64->32 logits MMA + fused dual softmax(11). MW=4, NW=1, MB=2, 128 thr.
// Writes kh, kv fp32 NCHW directly.
// ---------------------------------------------------------------------------
__global__ __launch_bounds__(128)
void kpred_fused_kernel(const __nv_bfloat16* __restrict__ in,
                        const uint2* __restrict__ wtF,
                        const float* __restrict__ bh, const float* __restrict__ bv,
                        float* __restrict__ kh_out, float* __restrict__ kv_out) {
    constexpr int C = 64, MW = 4, MB = 2, NP = 32;
    constexpr int THREADS = 128, PXT = 128;
    constexpr int SA = C + 8;
    constexpr int NBK = 4;
    constexpr int ASZ = (PXT + 2) * SA * 2;   // 18720 B per stage

    extern __shared__ char smem_raw[];
    const uint32_t sA0_u = smem_u32(smem_raw);

    const int tid = threadIdx.x;
    const int wid = tid >> 5;
    const int lane = tid & 31;
    const int wm = wid;           // NW=1
    const int x0 = blockIdx.x * PXT;
    const int y = blockIdx.y;
    const int b = blockIdx.z;

    float acc[MB * NBK][4];
#pragma unroll
    for (int i = 0; i < MB * NBK; i++)
#pragma unroll
        for (int q = 0; q < 4; q++) acc[i][q] = 0.f;

    stage_A<C, PXT, THREADS>(in, sA0_u,            b, y, 0, x0, tid);
    stage_A<C, PXT, THREADS>(in, sA0_u + ASZ,      b, y, 1, x0, tid);
    stage_A<C, PXT, THREADS>(in, sA0_u + 2 * ASZ,  b, y, 2, x0, tid);
    CP_COMMIT();
    CP_WAIT0();
    __syncthreads();

    compute_ky<C, MB, NP>(sA0_u,           wtF, 0, 0, wm, 0, lane, acc);
    compute_ky<C, MB, NP>(sA0_u + ASZ,     wtF, 1, 0, wm, 0, lane, acc);
    compute_ky<C, MB, NP>(sA0_u + 2 * ASZ, wtF, 2, 0, wm, 0, lane, acc);

    // ---- transpose through smem (stage buffers dead now), stride 34 to dodge conflicts
    __syncthreads();
    float* sS = (float*)smem_raw;      // need 128*34*4 = 17408 B <= ASZ
    const int g = lane >> 2;
    const int cpair = (lane & 3) * 2;
#pragma unroll
    for (int mb = 0; mb < MB; mb++) {
#pragma unroll
        for (int half = 0; half < 2; half++) {
            int m = wm * (MB * 16) + mb * 16 + g + half * 8;
#pragma unroll
            for (int nb = 0; nb < NBK; nb++) {
                int col = nb * 8 + cpair;
                sS[m * 34 + col]     = acc[mb * NBK + nb][half * 2 + 0];
                sS[m * 34 + col + 1] = acc[mb * NBK + nb][half * 2 + 1];
            }
        }
    }
    __syncthreads();

    // ---- per-pixel dual softmax (one pixel per thread)
    const int p = tid;
    const int x = x0 + p;
    float l[2 * KF];
#pragma unroll
    for (int i = 0; i < KF; i++)      l[i]      = sS[p * 34 + i] + bh[i];
#pragma unroll
    for (int i = 0; i < KF; i++)      l[KF + i] = sS[p * 34 + KF + i] + bv[i];
    {
        float mx = l[0];
#pragma unroll
        for (int i = 1; i < KF; i++) mx = fmaxf(mx, l[i]);
        float e[KF], s = 0.f;
#pragma unroll
        for (int i = 0; i < KF; i++) { e[i] = expf(l[i] - mx); s += e[i]; }
        float inv = 1.f / s;
#pragma unroll
        for (int i = 0; i < KF; i++)
            kh_out[(((size_t)b * KF + i) * H_ + y) * W_ + x] = e[i] * inv;
    }
    {
        float mx = l[KF];
#pragma unroll
        for (int i = 1; i < KF; i++) mx = fmaxf(mx, l[KF + i]);
        float e[KF], s = 0.f;
#pragma unroll
        for (int i = 0; i < KF; i++) { e[i] = expf(l[KF + i] - mx); s += e[i]; }
        float inv = 1.f / s;
#pragma unroll
        for (int i = 0; i < KF; i++)
            kv_out[(((size_t)b * KF + i) * H_ + y) * W_ + x] = e[i] * inv;
    }
}

// ---------------------------------------------------------------------------
// Separable blur + composite (fp32)
// ---------------------------------------------------------------------------
__global__ __launch_bounds__(256)
void hblur_kernel(const float* __restrict__ rgb, const float* __restrict__ kh,
                  float* __restrict__ hout) {
    __shared__ float srow[3][W_ + 10];
    const int x = threadIdx.x;
    const int y = blockIdx.x;
    const int b = blockIdx.y;

#pragma unroll
    for (int c = 0; c < 3; c++)
        srow[c][x + 5] = rgb[(((size_t)b * 3 + c) * H_ + y) * W_ + x];
    if (x < 5) {
#pragma unroll
        for (int c = 0; c < 3; c++) { srow[c][x] = 0.f; srow[c][W_ + 5 + x] = 0.f; }
    }
    __syncthreads();

    float k[KF];
#pragma unroll
    for (int i = 0; i < KF; i++)
        k[i] = kh[(((size_t)b * KF + i) * H_ + y) * W_ + x];

#pragma unroll
    for (int c = 0; c < 3; c++) {
        float s = 0.f;
#pragma unroll
        for (int i = 0; i < KF; i++) s = fmaf(k[i], srow[c][x + i], s);
        hout[(((size_t)b * 3 + c) * H_ + y) * W_ + x] = s;
    }
}

__global__ __launch_bounds__(256)
void vblur_kernel(const float* __restrict__ hbuf, const float* __restrict__ kv,
                  const float* __restrict__ rgb, const float* __restrict__ depth,
                  float* __restrict__ fin, float* __restrict__ blur,
                  float* __restrict__ mask) {
    const int x = threadIdx.x;
    const int y = blockIdx.x;
    const int b = blockIdx.y;

    float k[KF];
#pragma unroll
    for (int i = 0; i < KF; i++)
        k[i] = kv[(((size_t)b * KF + i) * H_ + y) * W_ + x];

    float d = depth[((size_t)b * H_ + y) * W_ + x];
    float m = (d > THRESH) ? 1.f : 0.f;

#pragma unroll
    for (int c = 0; c < 3; c++) {
        float s = 0.f;
#pragma unroll
        for (int i = 0; i < KF; i++) {
            int yy = y - 5 + i;
            if (yy >= 0 && yy < H_)
                s = fmaf(k[i], hbuf[(((size_t)b * 3 + c) * H_ + yy) * W_ + x], s);
        }
        size_t oidx = (((size_t)b * 3 + c) * H_ + y) * W_ + x;
        float r = rgb[oidx];
        blur[oidx] = s;
        fin[oidx] = m * r + (1.f - m) * s;
    }
    mask[((size_t)b * H_ + y) * W_ + x] = m;
}

// ---------------------------------------------------------------------------
extern "C" void kernel_launch(void* const* d_in, const int* in_sizes, int n_in,
                              void* d_out, int out_size) {
    const float* rgb   = (const float*)d_in[0];
    const float* depth = (const float*)d_in[1];
    const float* w1 = (const float*)d_in[2];
    const float* b1 = (const float*)d_in[3];
    const float* w2 = (const float*)d_in[4];
    const float* b2 = (const float*)d_in[5];
    const float* w3 = (const float*)d_in[6];
    const float* b3 = (const float*)d_in[7];
    const float* w4 = (const float*)d_in[8];
    const float* b4 = (const float*)d_in[9];
    const float* w5 = (const float*)d_in[10];
    const float* b5 = (const float*)d_in[11];
    const float* wh = (const float*)d_in[12];
    const float* bh = (const float*)d_in[13];
    const float* wv = (const float*)d_in[14];
    const float* bv = (const float*)d_in[15];

    float* out = (float*)d_out;
    float* fin_o  = out;
    float* blur_o = out + (size_t)B_ * 3 * HW;
    float* kh_o   = out + (size_t)2 * B_ * 3 * HW;
    float* kv_o   = kh_o + (size_t)B_ * KF * HW;
    float* mask_o = kv_o + (size_t)B_ * KF * HW;

    __nv_bfloat16 *bufA, *bufB;
    uint2 *wt1, *wt2, *wt3, *wt4, *wt5, *wtp;
    cudaGetSymbolAddress((void**)&bufA, g_bufA);
    cudaGetSymbolAddress((void**)&bufB, g_bufB);
    cudaGetSymbolAddress((void**)&wt1, g_wt1);
    cudaGetSymbolAddress((void**)&wt2, g_wt2);
    cudaGetSymbolAddress((void**)&wt3, g_wt3);
    cudaGetSymbolAddress((void**)&wt4, g_wt4);
    cudaGetSymbolAddress((void**)&wt5, g_wt5);
    cudaGetSymbolAddress((void**)&wtp, g_wtp);

    // smem: 3 stages of (PXT+2)x(C+8) bf16
    const int S_c1 = 3 * 130 * 24 * 2;    // conv1: PXT=128, C=16  (18720 B)
    const int S_c2 = 3 * 130 * 72 * 2;    // conv2: PXT=128, C=64  (56160 B)
    const int S_c3 = 3 * 130 * 72 * 2;    // conv3: PXT=128, C=64
    const int S_c4 = 3 * 130 * 136 * 2;   // conv4: PXT=128, C=128 (106080 B)
    const int S_c5 = 3 * 130 * 136 * 2;   // conv5: PXT=128, C=128
    const int S_kp = 3 * 130 * 72 * 2;    // kpred: PXT=128, C=64

    cudaFuncSetAttribute((const void*)convmma_kernel<16, 4, 2, 2, 64, true>,
                         cudaFuncAttributeMaxDynamicSharedMemorySize, S_c1);
    cudaFuncSetAttribute((const void*)convmma_kernel<64, 4, 2, 2, 64, true>,
                         cudaFuncAttributeMaxDynamicSharedMemorySize, S_c2);
    cudaFuncSetAttribute((const void*)convmma_kernel<64, 2, 4, 4, 128, true>,
                         cudaFuncAttributeMaxDynamicSharedMemorySize, S_c3);
    cudaFuncSetAttribute((const void*)convmma_kernel<128, 2, 4, 4, 128, true>,
                         cudaFuncAttributeMaxDynamicSharedMemorySize, S_c4);
    cudaFuncSetAttribute((const void*)convmma_kernel<128, 2, 2, 4, 64, true>,
                         cudaFuncAttributeMaxDynamicSharedMemorySize, S_c5);
    cudaFuncSetAttribute((const void*)kpred_fused_kernel,
                         cudaFuncAttributeMaxDynamicSharedMemorySize, S_kp);

    // launch 0: fused fragment-order weight packing (all 6 layers)
    {
        int total = (3 * 3 * 8 + 3 * 12 * 8 + 3 * 12 * 16 + 3 * 24 * 16 + 3 * 24 * 8 + 3 * 12 * 4) * 32;
        packall_kernel<<<(total + 255) / 256, 256>>>(w1, w2, w3, w4, w5, wh, wv,
                                                     wt1, wt2, wt3, wt4, wt5, wtp);
    }
    // launch 1: pack rgb+depth -> NHWC-16 bf16 (bufB)
    pack_input16_kernel<<<B_ * HW / 256, 256>>>(rgb, depth, bufB);

    // launch 2: conv1 16(4)->64 MMA (bufB -> bufA)
    convmma_kernel<16, 4, 2, 2, 64, true>
        <<<dim3(2, H_, B_), 256, S_c1>>>(bufB, wt1, b1, bufA);
    // launch 3: conv2 64->64 (bufA -> bufB)
    convmma_kernel<64, 4, 2, 2, 64, true>
        <<<dim3(2, H_, B_), 256, S_c2>>>(bufA, wt2, b2, bufB);
    // launch 4: conv3 64->128 (bufB -> bufA)
    convmma_kernel<64, 2, 4, 4, 128, true>
        <<<dim3(2, H_, B_), 256, S_c3>>>(bufB, wt3, b3, bufA);
    // launch 5: conv4 128->128 (bufA -> bufB)
    convmma_kernel<128, 2, 4, 4, 128, true>
        <<<dim3(2, H_, B_), 256, S_c4>>>(bufA, wt4, b4, bufB);
    // launch 6: conv5 128->64 (bufB -> bufA)
    convmma_kernel<128, 2, 2, 4, 64, true>
        <<<dim3(2, H_, B_), 128, S_c5>>>(bufB, wt5, b5, bufA);
    // launch 7: kpred + fused softmax -> kh, kv
    kpred_fused_kernel<<<dim3(2, H_, B_), 128, S_kp>>>(bufA, wtp, bh, bv, kh_o, kv_o);
    // launch 8/9: blur + composite (bufB reused as fp32 hbuf scratch)
    hblur_kernel<<<dim3(H_, B_), 256>>>(rgb, kh_o, (float*)bufB);
    vblur_kernel<<<dim3(H_, B_), 256>>>((float*)bufB, kv_o, rgb, depth, fin_o, blur_o, mask_o);
}

// round 16
// speedup vs baseline: 1.2152x; 1.0082x over previous
#include <cuda_runtime.h>
#include <cuda_bf16.h>
#include <cstdint>
#include <math.h>

#define H_ 256
#define W_ 256
#define B_ 8
#define HW (H_ * W_)
#define KF 11
#define THRESH 0.2f

// ---------------------------------------------------------------------------
// Device scratch (no allocation allowed)
// ---------------------------------------------------------------------------
__device__ __nv_bfloat16 g_bufA[(size_t)B_ * 128 * HW];   // NHWC activations ping
__device__ __nv_bfloat16 g_bufB[(size_t)B_ * 128 * HW];   // NHWC pong / x16 input / fp32 scratch
// Fragment-packed weights: [ky][s][n8][lane] -> uint2 (b0,b1 regs of m16n8k16)
__device__ uint2 g_wt1[3 * 3 * 8 * 32];      // CIN=16(pad4), NP=64
__device__ uint2 g_wt2[3 * 12 * 8 * 32];     // CIN=64,  NP=64
__device__ uint2 g_wt3[3 * 12 * 16 * 32];    // CIN=64,  NP=128
__device__ uint2 g_wt4[3 * 24 * 16 * 32];    // CIN=128, NP=128
__device__ uint2 g_wt5[3 * 24 * 8 * 32];     // CIN=128, NP=64
__device__ uint2 g_wtp[3 * 12 * 4 * 32];     // CIN=64,  NP=32

__device__ __forceinline__ uint32_t smem_u32(const void* p) {
    uint32_t a;
    asm("{ .reg .u64 t; cvta.to.shared.u64 t, %1; cvt.u32.u64 %0, t; }" : "=r"(a) : "l"(p));
    return a;
}

__device__ __forceinline__ void ldmatrix_x4(uint32_t* a, uint32_t addr) {
    asm volatile("ldmatrix.sync.aligned.m8n8.x4.shared.b16 {%0,%1,%2,%3}, [%4];"
                 : "=r"(a[0]), "=r"(a[1]), "=r"(a[2]), "=r"(a[3]) : "r"(addr));
}

__device__ __forceinline__ void mma_bf16(float* d, const uint32_t* a, const uint32_t* b) {
    asm volatile(
        "mma.sync.aligned.m16n8k16.row.col.f32.bf16.bf16.f32 "
        "{%0,%1,%2,%3}, {%4,%5,%6,%7}, {%8,%9}, {%0,%1,%2,%3};"
        : "+f"(d[0]), "+f"(d[1]), "+f"(d[2]), "+f"(d[3])
        : "r"(a[0]), "r"(a[1]), "r"(a[2]), "r"(a[3]), "r"(b[0]), "r"(b[1]));
}

__device__ __forceinline__ void cp16(uint32_t dst, const void* src, bool pred) {
    asm volatile("cp.async.cg.shared.global [%0], [%1], 16, %2;"
                 :: "r"(dst), "l"(src), "r"(pred ? 16 : 0));
}
#define CP_COMMIT() asm volatile("cp.async.commit_group;" ::: "memory")
#define CP_WAIT0()  asm volatile("cp.async.wait_group 0;" ::: "memory")

// ---------------------------------------------------------------------------
// Fragment-order weight packing: [ky][s][n8][lane] uint2.
// b0 = pair(k0,k0+1), b1 = pair(k0+8,k0+9); k0 = s*16+(lane&3)*2; n = n8*8+(lane>>2)
// ---------------------------------------------------------------------------
template <int CIN, int COUT, int NP>
__device__ __forceinline__ void packfrag(const float* __restrict__ w, uint2* __restrict__ wt, int i) {
    constexpr int NSTEP = 3 * CIN / 16;
    constexpr int NPG = NP / 8;
    int lane = i & 31;
    int n8 = (i >> 5) % NPG;
    int s = (i >> 5) / NPG % NSTEP;
    int ky = i / (32 * NPG * NSTEP);
    int n = n8 * 8 + (lane >> 2);
    int k0 = s * 16 + (lane & 3) * 2;
    float v[4];
#pragma unroll
    for (int j = 0; j < 4; j++) {
        int k = k0 + (j >> 1) * 8 + (j & 1);
        int kx = k / CIN, ci = k % CIN;
        v[j] = (n < COUT) ? w[((size_t)n * CIN + ci) * 9 + ky * 3 + kx] : 0.f;
    }
    __nv_bfloat162 lo = __floats2bfloat162_rn(v[0], v[1]);
    __nv_bfloat162 hi = __floats2bfloat162_rn(v[2], v[3]);
    uint2 r; r.x = *(uint32_t*)&lo; r.y = *(uint32_t*)&hi;
    wt[i] = r;
}

__global__ void packall_kernel(const float* __restrict__ w1,
                               const float* __restrict__ w2, const float* __restrict__ w3,
                               const float* __restrict__ w4, const float* __restrict__ w5,
                               const float* __restrict__ wh, const float* __restrict__ wv,
                               uint2* __restrict__ wt1,
                               uint2* __restrict__ wt2, uint2* __restrict__ wt3,
                               uint2* __restrict__ wt4, uint2* __restrict__ wt5,
                               uint2* __restrict__ wtp) {
    constexpr int N1 = 3 * 3 * 8 * 32;
    constexpr int N2 = 3 * 12 * 8 * 32;
    constexpr int N3 = 3 * 12 * 16 * 32;
    constexpr int N4 = 3 * 24 * 16 * 32;
    constexpr int N5 = 3 * 24 * 8 * 32;
    constexpr int NPP = 3 * 12 * 4 * 32;
    int i = blockIdx.x * 256 + threadIdx.x;
    if (i < N1) {
        // conv1: logical CIN=16, physical CIN=4 (channels 4..15 are zero-pad)
        constexpr int NSTEP = 3, NPG = 8;
        int lane = i & 31;
        int n8 = (i >> 5) % NPG;
        int s = (i >> 5) / NPG % NSTEP;
        int ky = i / (32 * NPG * NSTEP);
        int n = n8 * 8 + (lane >> 2);
        int k0 = s * 16 + (lane & 3) * 2;
        float v[4];
#pragma unroll
        for (int j = 0; j < 4; j++) {
            int k = k0 + (j >> 1) * 8 + (j & 1);
            int kx = k / 16, ci = k % 16;
            v[j] = (ci < 4) ? w1[((size_t)n * 4 + ci) * 9 + ky * 3 + kx] : 0.f;
        }
        __nv_bfloat162 lo = __floats2bfloat162_rn(v[0], v[1]);
        __nv_bfloat162 hi = __floats2bfloat162_rn(v[2], v[3]);
        uint2 r; r.x = *(uint32_t*)&lo; r.y = *(uint32_t*)&hi;
        wt1[i] = r;
        return;
    }
    i -= N1;
    if (i < N2) { packfrag<64, 64, 64>(w2, wt2, i); return; }
    i -= N2;
    if (i < N3) { packfrag<64, 128, 128>(w3, wt3, i); return; }
    i -= N3;
    if (i < N4) { packfrag<128, 128, 128>(w4, wt4, i); return; }
    i -= N4;
    if (i < N5) { packfrag<128, 64, 64>(w5, wt5, i); return; }
    i -= N5;
    if (i < NPP) {
        // kpred: n 0..10 = wh, 11..21 = wv, rest 0 (CIN=64, NP=32)
        constexpr int NSTEP = 12, NPG = 4;
        int lane = i & 31;
        int n8 = (i >> 5) % NPG;
        int s = (i >> 5) / NPG % NSTEP;
        int ky = i / (32 * NPG * NSTEP);
        int n = n8 * 8 + (lane >> 2);
        int k0 = s * 16 + (lane & 3) * 2;
        float v[4];
#pragma unroll
        for (int j = 0; j < 4; j++) {
            int k = k0 + (j >> 1) * 8 + (j & 1);
            int kx = k / 64, ci = k % 64;
            float val = 0.f;
            if (n < KF)          val = wh[((size_t)n * 64 + ci) * 9 + ky * 3 + kx];
            else if (n < 2 * KF) val = wv[((size_t)(n - KF) * 64 + ci) * 9 + ky * 3 + kx];
            v[j] = val;
        }
        __nv_bfloat162 lo = __floats2bfloat162_rn(v[0], v[1]);
        __nv_bfloat162 hi = __floats2bfloat162_rn(v[2], v[3]);
        uint2 r; r.x = *(uint32_t*)&lo; r.y = *(uint32_t*)&hi;
        wtp[i] = r;
    }
}

// ---------------------------------------------------------------------------
// Pack rgb+depth NCHW fp32 -> NHWC-16 bf16 (c0..2 rgb, c3 depth, c4..15 zero)
// ---------------------------------------------------------------------------
__global__ __launch_bounds__(256)
void pack_input16_kernel(const float* __restrict__ rgb, const float* __restrict__ depth,
                         __nv_bfloat16* __restrict__ out) {
    int gp = blockIdx.x * 256 + threadIdx.x;
    int px = gp % HW;
    int b = gp / HW;
    float r = rgb[((size_t)b * 3 + 0) * HW + px];
    float g = rgb[((size_t)b * 3 + 1) * HW + px];
    float bl = rgb[((size_t)b * 3 + 2) * HW + px];
    float d = depth[(size_t)b * HW + px];
    __nv_bfloat16* op = out + (size_t)gp * 16;
    __nv_bfloat162 p0 = __floats2bfloat162_rn(r, g);
    __nv_bfloat162 p1 = __floats2bfloat162_rn(bl, d);
    uint4 v0;
    v0.x = *(uint32_t*)&p0;
    v0.y = *(uint32_t*)&p1;
    v0.z = 0u; v0.w = 0u;
    *(uint4*)op = v0;
    *(uint4*)(op + 8) = make_uint4(0u, 0u, 0u, 0u);
}

// ---------------------------------------------------------------------------
// Stage one ky row's A im2col strip (PXT+2 pixels x C) via cp.async
// ---------------------------------------------------------------------------
template <int C, int PXT, int THREADS>
__device__ __forceinline__ void stage_A(const __nv_bfloat16* __restrict__ in,
                                        uint32_t sA_u, int b, int y, int ky,
                                        int x0, int tid) {
    constexpr int SA = C + 8;
    constexpr int CH8 = C / 8;
    const int yy = y + ky - 1;
    const bool rowok = ((unsigned)yy < H_);
    const __nv_bfloat16* inrow = in + (((size_t)b * H_ + (rowok ? yy : 0)) * W_) * C;
    for (int it = tid; it < (PXT + 2) * CH8; it += THREADS) {
        int p = it / CH8;
        int c8 = it - p * CH8;
        int xx = x0 + p - 1;
        bool ok = rowok && ((unsigned)xx < W_);
        cp16(sA_u + (p * SA + c8 * 8) * 2, inrow + (size_t)(ok ? xx : 0) * C + c8 * 8, ok);
    }
}

// ---------------------------------------------------------------------------
// Compute one ky row's MMA contribution (barrier-free; caller staged all rows)
// ---------------------------------------------------------------------------
template <int C, int MB, int NP>
__device__ __forceinline__ void compute_ky(uint32_t sA_u, const uint2* __restrict__ wtF,
                                           int ky, int n8_0, int wm, int wn, int lane,
                                           float (*acc)[4] /* [MB*4][4] */) {
    constexpr int SA = C + 8;
    constexpr int NSTEP = 3 * C / 16;
    constexpr int KXW = C / 16;
    constexpr int NBK = 4;
    constexpr int NPG = NP / 8;

    const int lane_row = lane & 15;
    const int colsel = (lane >> 4) * 8;
    const uint2* wbase = wtF + ((size_t)ky * NSTEP * NPG + n8_0 + wn * NBK) * 32 + lane;
    const int mrow0 = wm * (MB * 16);

#pragma unroll
    for (int s = 0; s < NSTEP; s++) {
        const int kx = s / KXW;
        const int c0 = (s - kx * KXW) * 16;
        uint32_t afr[MB][4];
#pragma unroll
        for (int mb = 0; mb < MB; mb++) {
            uint32_t addr = sA_u +
                ((mrow0 + mb * 16 + lane_row + kx) * SA + c0 + colsel) * 2;
            ldmatrix_x4(afr[mb], addr);
        }
        uint32_t bfr[NBK][2];
#pragma unroll
        for (int nb = 0; nb < NBK; nb++) {
            uint2 bv = __ldg(wbase + ((size_t)s * NPG + nb) * 32);
            bfr[nb][0] = bv.x;
            bfr[nb][1] = bv.y;
        }
#pragma unroll
        for (int mb = 0; mb < MB; mb++)
#pragma unroll
            for (int nb = 0; nb < NBK; nb++)
                mma_bf16(acc[mb * NBK + nb], afr[mb], bfr[nb]);
    }
}

// ---------------------------------------------------------------------------
// Implicit-GEMM 3x3 conv: 3 rows staged up front, barrier-free compute chain.
// CTA: (MW*MB*16) px x (NW*32) n. Warp = MB*16 px x 32 n.
// ---------------------------------------------------------------------------
template <int C, int MW, int NW, int MB, int NP, bool RELU>
__global__ __launch_bounds__(MW * NW * 32)
void convmma_kernel(const __nv_bfloat16* __restrict__ in,
                    const uint2* __restrict__ wtF,
                    const float* __restrict__ bias,
                    __nv_bfloat16* __restrict__ outp) {
    constexpr int THREADS = MW * NW * 32;
    constexpr int PXT = MW * MB * 16;
    constexpr int NTILE = NW * 32;
    constexpr int SA = C + 8;
    constexpr int NBK = 4;
    constexpr int ASZ = (PXT + 2) * SA * 2;

    extern __shared__ char smem_raw[];
    const uint32_t sA0_u = smem_u32(smem_raw);

    __shared__ float s_bias[NTILE];

    const int tid = threadIdx.x;
    const int wid = tid >> 5;
    const int lane = tid & 31;
    const int wm = wid % MW;
    const int wn = wid / MW;
    const int x0 = blockIdx.x * PXT;
    const int y = blockIdx.y;
    constexpr int NTILES = NP / NTILE;
    const int b = blockIdx.z / NTILES;
    const int n0 = (blockIdx.z % NTILES) * NTILE;
    const int n8_0 = n0 / 8;

    if (tid < NTILE) s_bias[tid] = bias[n0 + tid];

    float acc[MB * NBK][4];
#pragma unroll
    for (int i = 0; i < MB * NBK; i++)
#pragma unroll
        for (int q = 0; q < 4; q++) acc[i][q] = 0.f;

    stage_A<C, PXT, THREADS>(in, sA0_u,            b, y, 0, x0, tid);
    stage_A<C, PXT, THREADS>(in, sA0_u + ASZ,      b, y, 1, x0, tid);
    stage_A<C, PXT, THREADS>(in, sA0_u + 2 * ASZ,  b, y, 2, x0, tid);
    CP_COMMIT();
    CP_WAIT0();
    __syncthreads();

    compute_ky<C, MB, NP>(sA0_u,           wtF, 0, n8_0, wm, wn, lane, acc);
    compute_ky<C, MB, NP>(sA0_u + ASZ,     wtF, 1, n8_0, wm, wn, lane, acc);
    compute_ky<C, MB, NP>(sA0_u + 2 * ASZ, wtF, 2, n8_0, wm, wn, lane, acc);

    // ---- epilogue ----
    const int g = lane >> 2;
    const int cpair = (lane & 3) * 2;
#pragma unroll
    for (int mb = 0; mb < MB; mb++) {
#pragma unroll
        for (int half = 0; half < 2; half++) {
            int m = wm * (MB * 16) + mb * 16 + g + half * 8;
            size_t pix = ((size_t)b * H_ + y) * W_ + x0 + m;
#pragma unroll
            for (int nb = 0; nb < NBK; nb++) {
                int col = wn * 32 + nb * 8 + cpair;
                float f0 = acc[mb * NBK + nb][half * 2 + 0] + s_bias[col];
                float f1 = acc[mb * NBK + nb][half * 2 + 1] + s_bias[col + 1];
                if (RELU) { f0 = fmaxf(f0, 0.f); f1 = fmaxf(f1, 0.f); }
                __nv_bfloat162 h = __floats2bfloat162_rn(f0, f1);
                __nv_bfloat16* op = outp + pix * NP + n0 + col;
                *(uint32_t*)op = *(uint32_t*)&h;
            }
        }
    }
}

// ---------------------------------------------------------------------------
// kpred: 64->32 logits MMA + fused dual softmax(11). MW=4, NW=1, MB=2, 128 thr.
// Writes kh, kv fp32 NCHW directly.
// ---------------------------------------------------------------------------
__global__ __launch_bounds__(128)
void kpred_fused_kernel(const __nv_bfloat16* __restrict__ in,
                        const uint2* __restrict__ wtF,
                        const float* __restrict__ bh, const float* __restrict__ bv,
                        float* __restrict__ kh_out, float* __restrict__ kv_out) {
    constexpr int C = 64, MW = 4, MB = 2, NP = 32;
    constexpr int THREADS = 128, PXT = 128;
    constexpr int SA = C + 8;
    constexpr int NBK = 4;
    constexpr int ASZ = (PXT + 2) * SA * 2;   // 18720 B per stage

    extern __shared__ char smem_raw[];
    const uint32_t sA0_u = smem_u32(smem_raw);

    const int tid = threadIdx.x;
    const int wid = tid >> 5;
    const int lane = tid & 31;
    const int wm = wid;           // NW=1
    const int x0 = blockIdx.x * PXT;
    const int y = blockIdx.y;
    const int b = blockIdx.z;

    float acc[MB * NBK][4];
#pragma unroll
    for (int i = 0; i < MB * NBK; i++)
#pragma unroll
        for (int q = 0; q < 4; q++) acc[i][q] = 0.f;

    stage_A<C, PXT, THREADS>(in, sA0_u,            b, y, 0, x0, tid);
    stage_A<C, PXT, THREADS>(in, sA0_u + ASZ,      b, y, 1, x0, tid);
    stage_A<C, PXT, THREADS>(in, sA0_u + 2 * ASZ,  b, y, 2, x0, tid);
    CP_COMMIT();
    CP_WAIT0();
    __syncthreads();

    compute_ky<C, MB, NP>(sA0_u,           wtF, 0, 0, wm, 0, lane, acc);
    compute_ky<C, MB, NP>(sA0_u + ASZ,     wtF, 1, 0, wm, 0, lane, acc);
    compute_ky<C, MB, NP>(sA0_u + 2 * ASZ, wtF, 2, 0, wm, 0, lane, acc);

    // ---- transpose through smem (stage buffers dead now), stride 34 to dodge conflicts
    __syncthreads();
    float* sS = (float*)smem_raw;      // need 128*34*4 = 17408 B <= ASZ
    const int g = lane >> 2;
    const int cpair = (lane & 3) * 2;
#pragma unroll
    for (int mb = 0; mb < MB; mb++) {
#pragma unroll
        for (int half = 0; half < 2; half++) {
            int m = wm * (MB * 16) + mb * 16 + g + half * 8;
#pragma unroll
            for (int nb = 0; nb < NBK; nb++) {
                int col = nb * 8 + cpair;
                sS[m * 34 + col]     = acc[mb * NBK + nb][half * 2 + 0];
                sS[m * 34 + col + 1] = acc[mb * NBK + nb][half * 2 + 1];
            }
        }
    }
    __syncthreads();

    // ---- per-pixel dual softmax (one pixel per thread)
    const int p = tid;
    const int x = x0 + p;
    float l[2 * KF];
#pragma unroll
    for (int i = 0; i < KF; i++)      l[i]      = sS[p * 34 + i] + bh[i];
#pragma unroll
    for (int i = 0; i < KF; i++)      l[KF + i] = sS[p * 34 + KF + i] + bv[i];
    {
        float mx = l[0];
#pragma unroll
        for (int i = 1; i < KF; i++) mx = fmaxf(mx, l[i]);
        float e[KF], s = 0.f;
#pragma unroll
        for (int i = 0; i < KF; i++) { e[i] = expf(l[i] - mx); s += e[i]; }
        float inv = 1.f / s;
#pragma unroll
        for (int i = 0; i < KF; i++)
            kh_out[(((size_t)b * KF + i) * H_ + y) * W_ + x] = e[i] * inv;
    }
    {
        float mx = l[KF];
#pragma unroll
        for (int i = 1; i < KF; i++) mx = fmaxf(mx, l[KF + i]);
        float e[KF], s = 0.f;
#pragma unroll
        for (int i = 0; i < KF; i++) { e[i] = expf(l[KF + i] - mx); s += e[i]; }
        float inv = 1.f / s;
#pragma unroll
        for (int i = 0; i < KF; i++)
            kv_out[(((size_t)b * KF + i) * H_ + y) * W_ + x] = e[i] * inv;
    }
}

// ---------------------------------------------------------------------------
// Separable blur + composite (fp32)
// ---------------------------------------------------------------------------
__global__ __launch_bounds__(256)
void hblur_kernel(const float* __restrict__ rgb, const float* __restrict__ kh,
                  float* __restrict__ hout) {
    __shared__ float srow[3][W_ + 10];
    const int x = threadIdx.x;
    const int y = blockIdx.x;
    const int b = blockIdx.y;

#pragma unroll
    for (int c = 0; c < 3; c++)
        srow[c][x + 5] = rgb[(((size_t)b * 3 + c) * H_ + y) * W_ + x];
    if (x < 5) {
#pragma unroll
        for (int c = 0; c < 3; c++) { srow[c][x] = 0.f; srow[c][W_ + 5 + x] = 0.f; }
    }
    __syncthreads();

    float k[KF];
#pragma unroll
    for (int i = 0; i < KF; i++)
        k[i] = kh[(((size_t)b * KF + i) * H_ + y) * W_ + x];

#pragma unroll
    for (int c = 0; c < 3; c++) {
        float s = 0.f;
#pragma unroll
        for (int i = 0; i < KF; i++) s = fmaf(k[i], srow[c][x + i], s);
        hout[(((size_t)b * 3 + c) * H_ + y) * W_ + x] = s;
    }
}

__global__ __launch_bounds__(256)
void vblur_kernel(const float* __restrict__ hbuf, const float* __restrict__ kv,
                  const float* __restrict__ rgb, const float* __restrict__ depth,
                  float* __restrict__ fin, float* __restrict__ blur,
                  float* __restrict__ mask) {
    const int x = threadIdx.x;
    const int y = blockIdx.x;
    const int b = blockIdx.y;

    float k[KF];
#pragma unroll
    for (int i = 0; i < KF; i++)
        k[i] = kv[(((size_t)b * KF + i) * H_ + y) * W_ + x];

    float d = depth[((size_t)b * H_ + y) * W_ + x];
    float m = (d > THRESH) ? 1.f : 0.f;

#pragma unroll
    for (int c = 0; c < 3; c++) {
        float s = 0.f;
#pragma unroll
        for (int i = 0; i < KF; i++) {
            int yy = y - 5 + i;
            if (yy >= 0 && yy < H_)
                s = fmaf(k[i], hbuf[(((size_t)b * 3 + c) * H_ + yy) * W_ + x], s);
        }
        size_t oidx = (((size_t)b * 3 + c) * H_ + y) * W_ + x;
        float r = rgb[oidx];
        blur[oidx] = s;
        fin[oidx] = m * r + (1.f - m) * s;
    }
    mask[((size_t)b * H_ + y) * W_ + x] = m;
}

// ---------------------------------------------------------------------------
extern "C" void kernel_launch(void* const* d_in, const int* in_sizes, int n_in,
                              void* d_out, int out_size) {
    const float* rgb   = (const float*)d_in[0];
    const float* depth = (const float*)d_in[1];
    const float* w1 = (const float*)d_in[2];
    const float* b1 = (const float*)d_in[3];
    const float* w2 = (const float*)d_in[4];
    const float* b2 = (const float*)d_in[5];
    const float* w3 = (const float*)d_in[6];
    const float* b3 = (const float*)d_in[7];
    const float* w4 = (const float*)d_in[8];
    const float* b4 = (const float*)d_in[9];
    const float* w5 = (const float*)d_in[10];
    const float* b5 = (const float*)d_in[11];
    const float* wh = (const float*)d_in[12];
    const float* bh = (const float*)d_in[13];
    const float* wv = (const float*)d_in[14];
    const float* bv = (const float*)d_in[15];

    float* out = (float*)d_out;
    float* fin_o  = out;
    float* blur_o = out + (size_t)B_ * 3 * HW;
    float* kh_o   = out + (size_t)2 * B_ * 3 * HW;
    float* kv_o   = kh_o + (size_t)B_ * KF * HW;
    float* mask_o = kv_o + (size_t)B_ * KF * HW;

    __nv_bfloat16 *bufA, *bufB;
    uint2 *wt1, *wt2, *wt3, *wt4, *wt5, *wtp;
    cudaGetSymbolAddress((void**)&bufA, g_bufA);
    cudaGetSymbolAddress((void**)&bufB, g_bufB);
    cudaGetSymbolAddress((void**)&wt1, g_wt1);
    cudaGetSymbolAddress((void**)&wt2, g_wt2);
    cudaGetSymbolAddress((void**)&wt3, g_wt3);
    cudaGetSymbolAddress((void**)&wt4, g_wt4);
    cudaGetSymbolAddress((void**)&wt5, g_wt5);
    cudaGetSymbolAddress((void**)&wtp, g_wtp);

    // smem: 3 stages of (PXT+2)x(C+8) bf16
    const int S_c1 = 3 * 130 * 24 * 2;    // conv1: PXT=128, C=16  (18720 B)
    const int S_c2 = 3 * 130 * 72 * 2;    // conv2: PXT=128, C=64  (56160 B)
    const int S_c3 = 3 * 130 * 72 * 2;    // conv3: PXT=128, C=64
    const int S_c4 = 3 * 130 * 136 * 2;   // conv4: PXT=128, C=128 (106080 B)
    const int S_c5 = 3 * 130 * 136 * 2;   // conv5: PXT=128, C=128
    const int S_kp = 3 * 130 * 72 * 2;    // kpred: PXT=128, C=64

    cudaFuncSetAttribute((const void*)convmma_kernel<16, 2, 2, 4, 64, true>,
                         cudaFuncAttributeMaxDynamicSharedMemorySize, S_c1);
    cudaFuncSetAttribute((const void*)convmma_kernel<64, 2, 2, 4, 64, true>,
                         cudaFuncAttributeMaxDynamicSharedMemorySize, S_c2);
    cudaFuncSetAttribute((const void*)convmma_kernel<64, 2, 4, 4, 128, true>,
                         cudaFuncAttributeMaxDynamicSharedMemorySize, S_c3);
    cudaFuncSetAttribute((const void*)convmma_kernel<128, 2, 4, 4, 128, true>,
                         cudaFuncAttributeMaxDynamicSharedMemorySize, S_c4);
    cudaFuncSetAttribute((const void*)convmma_kernel<128, 2, 2, 4, 64, true>,
                         cudaFuncAttributeMaxDynamicSharedMemorySize, S_c5);
    cudaFuncSetAttribute((const void*)kpred_fused_kernel,
                         cudaFuncAttributeMaxDynamicSharedMemorySize, S_kp);

    // launch 0: fused fragment-order weight packing (all 6 layers)
    {
        int total = (3 * 3 * 8 + 3 * 12 * 8 + 3 * 12 * 16 + 3 * 24 * 16 + 3 * 24 * 8 + 3 * 12 * 4) * 32;
        packall_kernel<<<(total + 255) / 256, 256>>>(w1, w2, w3, w4, w5, wh, wv,
                                                     wt1, wt2, wt3, wt4, wt5, wtp);
    }
    // launch 1: pack rgb+depth -> NHWC-16 bf16 (bufB)
    pack_input16_kernel<<<B_ * HW / 256, 256>>>(rgb, depth, bufB);

    // launch 2: conv1 16(4)->64 MMA, MB=4 shape (bufB -> bufA)
    convmma_kernel<16, 2, 2, 4, 64, true>
        <<<dim3(2, H_, B_), 128, S_c1>>>(bufB, wt1, b1, bufA);
    // launch 3: conv2 64->64, MB=4 shape (bufA -> bufB)
    convmma_kernel<64, 2, 2, 4, 64, true>
        <<<dim3(2, H_, B_), 128, S_c2>>>(bufA, wt2, b2, bufB);
    // launch 4: conv3 64->128 (bufB -> bufA)
    convmma_kernel<64, 2, 4, 4, 128, true>
        <<<dim3(2, H_, B_), 256, S_c3>>>(bufB, wt3, b3, bufA);
    // launch 5: conv4 128->128 (bufA -> bufB)
    convmma_kernel<128, 2, 4, 4, 128, true>
        <<<dim3(2, H_, B_), 256, S_c4>>>(bufA, wt4, b4, bufB);
    // launch 6: conv5 128->64 (bufB -> bufA)
    convmma_kernel<128, 2, 2, 4, 64, true>
        <<<dim3(2, H_, B_), 128, S_c5>>>(bufB, wt5, b5, bufA);
    // launch 7: kpred + fused softmax -> kh, kv
    kpred_fused_kernel<<<dim3(2, H_, B_), 128, S_kp>>>(bufA, wtp, bh, bv, kh_o, kv_o);
    // launch 8/9: blur + composite (bufB reused as fp32 hbuf scratch)
    hblur_kernel<<<dim3(H_, B_), 256>>>(rgb, kh_o, (float*)bufB);
    vblur_kernel<<<dim3(H_, B_), 256>>>((float*)bufB, kv_o, rgb, depth, fin_o, blur_o, mask_o);
}